// round 8
// baseline (speedup 1.0000x reference)
#include <cuda_runtime.h>
#include <cstdint>
#include <cstddef>

#define BB 8
#define LL 2048
#define HH 256
#define ROWS 64
#define JT 64
#define NT (LL / JT)
#define WST 258

// P layout: row stride 576 B (mod 128 = 64), 16-j group stride 144 B (mod 128 = 16)
#define PROWB 576
#define PGRPB 144

typedef unsigned long long ull;

// -------- scratch (no allocations allowed: __device__ globals) --------
__device__ float g_base[LL];
__device__ float g_st[BB * LL];
__device__ float g_so[BB * LL];
__device__ float g_mult[BB * LL];

// ---------------------------------------------------------------------
// f32x2 helpers (Blackwell packed fp32 pipe)
// ---------------------------------------------------------------------
__device__ __forceinline__ ull pack_dup(float p) {
    ull r;
    asm("mov.b64 %0, {%1, %1};" : "=l"(r) : "f"(p));
    return r;
}
__device__ __forceinline__ void fma2(ull& d, ull a, ull b) {
    asm("fma.rn.f32x2 %0, %1, %2, %0;" : "+l"(d) : "l"(a), "l"(b));
}
__device__ __forceinline__ void unpack2(ull v, float& lo, float& hi) {
    asm("mov.b64 {%0, %1}, %2;" : "=f"(lo), "=f"(hi) : "l"(v));
}

// ---------------------------------------------------------------------
// Kernel 0: base table + per-token column multiplier
// ---------------------------------------------------------------------
__global__ void k_base_mult(const int* __restrict__ pos) {
    int i = blockIdx.x * blockDim.x + threadIdx.x;
    if (i < LL) {
        g_base[i] = (i == 0) ? 0.5f : (1.0f / log2f(2.0f + (float)i));
    }
    if (i < BB * LL) {
        const unsigned long long mask =
            (1ULL << 19) | (1ULL << 20) | (1ULL << 21) |
            (1ULL << 33) | (1ULL << 34) | (1ULL << 35) |
            (1ULL << 41) | (1ULL << 42) | (1ULL << 43) |
            (1ULL << 44) | (1ULL << 45) | (1ULL << 46);
        int p = pos[i];
        bool op = (p >= 0) && (p < 64) && (((mask >> p) & 1ULL) != 0ULL);
        g_mult[i] = op ? 8.0f : 1.0f;
    }
}

// ---------------------------------------------------------------------
// Kernel 1: fused per-token transforms (y=0 -> st, y=1 -> so)
// ---------------------------------------------------------------------
__global__ __launch_bounds__(256)
void k_transform2(const float* __restrict__ text, const float* __restrict__ opinion,
                  const float* __restrict__ Wt, const float* __restrict__ bt,
                  const float* __restrict__ Wo, const float* __restrict__ wa,
                  const float* __restrict__ ba) {
    __shared__ float Ws[32 * WST];
    __shared__ float Xs[32 * 36];
    __shared__ float bias_s[256];
    __shared__ float wa_s[256];

    int which = blockIdx.y;
    const float* X = which ? opinion : text;
    const float* W = which ? Wo : Wt;
    const float* wav = which ? (wa + HH) : wa;

    int tid = threadIdx.x;
    int tx = tid & 31, ty = tid >> 5;
    int tok0 = blockIdx.x * 32;

    bias_s[tid] = which ? 0.0f : bt[tid];
    wa_s[tid] = wav[tid];

    ull acc2[4][4];
#pragma unroll
    for (int q = 0; q < 4; ++q)
#pragma unroll
        for (int m = 0; m < 4; ++m) acc2[q][m] = 0ULL;

    int kkl = tid & 31;
    int hb = tid >> 5;

    for (int k0 = 0; k0 < 256; k0 += 32) {
        __syncthreads();
#pragma unroll
        for (int r = 0; r < 32; ++r) {
            int h = hb + r * 8;
            Ws[kkl * WST + h] = W[h * 256 + k0 + kkl];
        }
#pragma unroll
        for (int r = 0; r < 4; ++r) {
            int idx = r * 256 + tid;
            int tok = idx >> 5, kk = idx & 31;
            Xs[tok * 36 + kk] = X[(size_t)(tok0 + tok) * 256 + k0 + kk];
        }
        __syncthreads();
#pragma unroll 8
        for (int kk = 0; kk < 32; ++kk) {
            ull wv[4];
#pragma unroll
            for (int m = 0; m < 4; ++m)
                wv[m] = *(const ull*)(Ws + kk * WST + tx * 2 + 64 * m);
            ull xd[4];
#pragma unroll
            for (int q = 0; q < 4; ++q)
                xd[q] = pack_dup(Xs[(ty * 4 + q) * 36 + kk]);
#pragma unroll
            for (int q = 0; q < 4; ++q)
#pragma unroll
                for (int m = 0; m < 4; ++m)
                    fma2(acc2[q][m], xd[q], wv[m]);
        }
    }

    float e = which ? ba[0] : 0.0f;
    float part[4];
#pragma unroll
    for (int q = 0; q < 4; ++q) {
        float s = 0.0f;
#pragma unroll
        for (int m = 0; m < 4; ++m) {
            int h = tx * 2 + 64 * m;
            float a0, a1;
            unpack2(acc2[q][m], a0, a1);
            s += tanhf(a0 + bias_s[h]) * wa_s[h];
            s += tanhf(a1 + bias_s[h + 1]) * wa_s[h + 1];
        }
        part[q] = s;
    }
#pragma unroll
    for (int off = 16; off; off >>= 1) {
#pragma unroll
        for (int q = 0; q < 4; ++q)
            part[q] += __shfl_xor_sync(0xffffffffu, part[q], off);
    }
    if (tx == 0) {
        float* outp = which ? g_so : g_st;
#pragma unroll
        for (int q = 0; q < 4; ++q)
            outp[tok0 + ty * 4 + q] = part[q] + e;
    }
}

// ---------------------------------------------------------------------
// Kernel 2: attention, no-max softmax (bounded scores), smem msom,
// warp-local P with conflict-free 576/144 layout, f32x2 PV.
// 256 threads, 64 rows/CTA, JT=64 double-buffered cp.async.
// ---------------------------------------------------------------------
__device__ __forceinline__ void cp16(float* s, const float* g) {
    unsigned sa = (unsigned)__cvta_generic_to_shared(s);
    asm volatile("cp.async.cg.shared.global [%0], [%1], 16;\n" ::"r"(sa), "l"(g));
}

#define VS_FLOATS (2 * JT * HH)                 // 32768 floats = 131072 B
#define P_BYTES   (ROWS * PROWB)                // 36864 B
#define MSOM_BYTES (LL * 8 + (LL / 16) * 16)    // 18432 B
#define ATTN_SMEM (VS_FLOATS * 4 + P_BYTES + LL * 4 + MSOM_BYTES + ROWS * 4)

__global__ __launch_bounds__(256, 1)
void k_attn(const float* __restrict__ V, float* __restrict__ out) {
    extern __shared__ float sm[];
    float* Vs = sm;                                   // 131072 B
    char*  Pb = (char*)(Vs + VS_FLOATS);              // P, 36864 B
    float* base_s = (float*)(Pb + P_BYTES);           // 8192 B
    char*  msom = (char*)(base_s + LL);               // 18432 B
    float* S_s = (float*)(msom + MSOM_BYTES);         // 256 B

    int tid = threadIdx.x;
    int tx = tid & 31, ty = tid >> 5;                 // ty 0..7
    int b = blockIdx.x >> 5;
    int row0 = (blockIdx.x & 31) * ROWS;

    const float* Vg = V + (size_t)b * LL * HH;
    const float* sog = g_so + b * LL;
    const float* mug = g_mult + b * LL;

    // preamble: base table + msom (swizzled: j*8 + (j>>4)*16)
    for (int i = tid; i < LL; i += 256) {
        base_s[i] = g_base[i];
        float m = mug[i];
        float so = sog[i];
        *(float2*)(msom + (size_t)i * 8 + (i >> 4) * 16) = make_float2(m, so * m);
    }

    // prefetch tile 0 (64 j x 256 feat = 64KB)
#pragma unroll
    for (int r = 0; r < 16; ++r) {
        int c = r * 256 + tid;
        cp16(Vs + c * 4, Vg + c * 4);
    }
    asm volatile("cp.async.commit_group;\n");

    // score mapping: 4 threads per row, 16 consecutive j each
    int sr = tid >> 2;              // 0..63
    int g = tid & 3;                // 16-j group
    float sti = g_st[b * LL + row0 + sr];
    int gi = row0 + sr;
    char* pwr = Pb + sr * PROWB + g * PGRPB;   // this thread's P slot (constant)
    float sum_reg = 0.0f;

    ull acc[8][4];
#pragma unroll
    for (int r = 0; r < 8; ++r)
#pragma unroll
        for (int m = 0; m < 4; ++m) acc[r][m] = 0ULL;

    __syncthreads();   // base_s / msom visible

    for (int t = 0; t < NT; ++t) {
        if (t) __syncthreads();     // all PV(t-1) reads done before buffer reuse
        int jb = t * JT + g * 16;

        // ---- score phase: 16 scores, no max subtraction ----
        const char* mb = msom + (size_t)t * 576 + g * 144;  // = jb*8 + (jb>>4)*16
#pragma unroll
        for (int u = 0; u < 8; ++u) {
            float4 q = *(const float4*)(mb + u * 16);   // {m0, som0, m1, som1}
            int j = jb + 2 * u;
            int d0 = gi - j;     d0 = (d0 < 0) ? -d0 : d0;
            int d1 = gi - j - 1; d1 = (d1 < 0) ? -d1 : d1;
            float s0 = base_s[d0] * fmaf(sti, q.x, q.y);
            float s1 = base_s[d1] * fmaf(sti, q.z, q.w);
            float p0 = __expf(s0);
            float p1 = __expf(s1);
            sum_reg += p0 + p1;
            *(float4*)(pwr + u * 16) = make_float4(p0, p0, p1, p1);
        }

        // ---- prefetch next V tile ----
        if (t + 1 < NT) {
            float* Vn = Vs + ((t + 1) & 1) * JT * HH;
            const float* gs = Vg + (size_t)(t + 1) * JT * HH;
#pragma unroll
            for (int r = 0; r < 16; ++r) {
                int c = r * 256 + tid;
                cp16(Vn + c * 4, gs + c * 4);
            }
            asm volatile("cp.async.commit_group;\n");
            asm volatile("cp.async.wait_group 1;\n");
        } else {
            asm volatile("cp.async.wait_group 0;\n");
        }
        __syncthreads();  // V tile complete for all threads

        // ---- PV phase: 8 rows x (4+4) feats, warp-local P ----
        const ulonglong2* Vb = (const ulonglong2*)(Vs + (t & 1) * JT * HH);
        const char* Pv = Pb + ty * 8 * PROWB;
        for (int g2 = 0; g2 < 4; ++g2) {
            const char* Pg = Pv + g2 * PGRPB;
#pragma unroll
            for (int u2 = 0; u2 < 8; ++u2) {
                int jj = g2 * 16 + u2 * 2;
                ulonglong2 u00 = Vb[(size_t)jj * 64 + tx];
                ulonglong2 u01 = Vb[(size_t)jj * 64 + 32 + tx];
                ulonglong2 u10 = Vb[(size_t)(jj + 1) * 64 + tx];
                ulonglong2 u11 = Vb[(size_t)(jj + 1) * 64 + 32 + tx];
#pragma unroll
                for (int r = 0; r < 8; ++r) {
                    ulonglong2 pp = *(const ulonglong2*)(Pg + r * PROWB + u2 * 16);
                    fma2(acc[r][0], pp.x, u00.x);
                    fma2(acc[r][1], pp.x, u00.y);
                    fma2(acc[r][2], pp.x, u01.x);
                    fma2(acc[r][3], pp.x, u01.y);
                    fma2(acc[r][0], pp.y, u10.x);
                    fma2(acc[r][1], pp.y, u10.y);
                    fma2(acc[r][2], pp.y, u11.x);
                    fma2(acc[r][3], pp.y, u11.y);
                }
            }
        }
    }

    // ---- row sums: reduce 4 threads per row ----
    sum_reg += __shfl_xor_sync(0xffffffffu, sum_reg, 1);
    sum_reg += __shfl_xor_sync(0xffffffffu, sum_reg, 2);
    if ((tid & 3) == 0) S_s[sr] = sum_reg;
    __syncthreads();

    // ---- epilogue: normalize and store ----
    float* Ob = out + ((size_t)b * LL + row0) * HH;
#pragma unroll
    for (int r = 0; r < 8; ++r) {
        int row = ty * 8 + r;
        float inv = 1.0f / S_s[row];
        float4 o0, o1;
        unpack2(acc[r][0], o0.x, o0.y);
        unpack2(acc[r][1], o0.z, o0.w);
        unpack2(acc[r][2], o1.x, o1.y);
        unpack2(acc[r][3], o1.z, o1.w);
        o0.x *= inv; o0.y *= inv; o0.z *= inv; o0.w *= inv;
        o1.x *= inv; o1.y *= inv; o1.z *= inv; o1.w *= inv;
        *(float4*)(Ob + (size_t)row * HH + tx * 4) = o0;
        *(float4*)(Ob + (size_t)row * HH + 128 + tx * 4) = o1;
    }
}

// ---------------------------------------------------------------------
extern "C" void kernel_launch(void* const* d_in, const int* in_sizes, int n_in,
                              void* d_out, int out_size) {
    const float* opinion = (const float*)d_in[0];
    const float* text    = (const float*)d_in[1];
    const int*   pos     = (const int*)d_in[2];
    const float* Wt      = (const float*)d_in[3];
    const float* bt      = (const float*)d_in[4];
    const float* Wo      = (const float*)d_in[5];
    const float* wa      = (const float*)d_in[6];
    const float* ba      = (const float*)d_in[7];
    float* out = (float*)d_out;

    cudaFuncSetAttribute(k_attn, cudaFuncAttributeMaxDynamicSharedMemorySize,
                         ATTN_SMEM);

    k_base_mult<<<(BB * LL + 255) / 256, 256>>>(pos);
    k_transform2<<<dim3(BB * LL / 32, 2), 256>>>(text, opinion, Wt, bt, Wo, wa, ba);
    k_attn<<<BB * (LL / ROWS), 256, ATTN_SMEM>>>(opinion, out);
}

// round 9
// speedup vs baseline: 1.9257x; 1.9257x over previous
#include <cuda_runtime.h>
#include <cstdint>
#include <cstddef>

#define BB 8
#define LL 2048
#define HH 256
#define ROWS 64
#define JT 32
#define NTT (LL / JT)     // 64 tiles
#define NP 260            // Vsp row stride in float2 units (conflict-free LDS.64)
#define WST 258

typedef unsigned long long ull;

// -------- scratch (no allocations allowed: __device__ globals) --------
__device__ float g_base[LL];
__device__ float g_st[BB * LL];
__device__ float g_so[BB * LL];
__device__ float g_mult[BB * LL];

// ---------------------------------------------------------------------
// helpers
// ---------------------------------------------------------------------
__device__ __forceinline__ ull pack_dup(float p) {
    ull r;
    asm("mov.b64 %0, {%1, %1};" : "=l"(r) : "f"(p));
    return r;
}
__device__ __forceinline__ void fma2(ull& d, ull a, ull b) {
    asm("fma.rn.f32x2 %0, %1, %2, %0;" : "+l"(d) : "l"(a), "l"(b));
}
__device__ __forceinline__ void unpack2(ull v, float& lo, float& hi) {
    asm("mov.b64 {%0, %1}, %2;" : "=f"(lo), "=f"(hi) : "l"(v));
}
__device__ __forceinline__ unsigned cvt_tf32(float x) {
    unsigned r;
    asm("cvt.rna.tf32.f32 %0, %1;" : "=r"(r) : "f"(x));
    return r;
}
__device__ __forceinline__ void mma_tf32(float* c, unsigned a0, unsigned a1,
                                         unsigned a2, unsigned a3,
                                         unsigned b0, unsigned b1) {
    asm volatile(
        "mma.sync.aligned.m16n8k8.row.col.f32.tf32.tf32.f32 "
        "{%0,%1,%2,%3}, {%4,%5,%6,%7}, {%8,%9}, {%0,%1,%2,%3};"
        : "+f"(c[0]), "+f"(c[1]), "+f"(c[2]), "+f"(c[3])
        : "r"(a0), "r"(a1), "r"(a2), "r"(a3), "r"(b0), "r"(b1));
}
__device__ __forceinline__ void cp16(float* s, const float* g) {
    unsigned sa = (unsigned)__cvta_generic_to_shared(s);
    asm volatile("cp.async.cg.shared.global [%0], [%1], 16;\n" ::"r"(sa), "l"(g));
}

// ---------------------------------------------------------------------
// Kernel 0: base table + per-token column multiplier
// ---------------------------------------------------------------------
__global__ void k_base_mult(const int* __restrict__ pos) {
    int i = blockIdx.x * blockDim.x + threadIdx.x;
    if (i < LL) {
        g_base[i] = (i == 0) ? 0.5f : (1.0f / log2f(2.0f + (float)i));
    }
    if (i < BB * LL) {
        const unsigned long long mask =
            (1ULL << 19) | (1ULL << 20) | (1ULL << 21) |
            (1ULL << 33) | (1ULL << 34) | (1ULL << 35) |
            (1ULL << 41) | (1ULL << 42) | (1ULL << 43) |
            (1ULL << 44) | (1ULL << 45) | (1ULL << 46);
        int p = pos[i];
        bool op = (p >= 0) && (p < 64) && (((mask >> p) & 1ULL) != 0ULL);
        g_mult[i] = op ? 8.0f : 1.0f;
    }
}

// ---------------------------------------------------------------------
// Kernel 1: fused per-token transforms (y=0 -> st, y=1 -> so)
// ---------------------------------------------------------------------
__global__ __launch_bounds__(256)
void k_transform2(const float* __restrict__ text, const float* __restrict__ opinion,
                  const float* __restrict__ Wt, const float* __restrict__ bt,
                  const float* __restrict__ Wo, const float* __restrict__ wa,
                  const float* __restrict__ ba) {
    __shared__ float Ws[32 * WST];
    __shared__ float Xs[32 * 36];
    __shared__ float bias_s[256];
    __shared__ float wa_s[256];

    int which = blockIdx.y;
    const float* X = which ? opinion : text;
    const float* W = which ? Wo : Wt;
    const float* wav = which ? (wa + HH) : wa;

    int tid = threadIdx.x;
    int tx = tid & 31, ty = tid >> 5;
    int tok0 = blockIdx.x * 32;

    bias_s[tid] = which ? 0.0f : bt[tid];
    wa_s[tid] = wav[tid];

    ull acc2[4][4];
#pragma unroll
    for (int q = 0; q < 4; ++q)
#pragma unroll
        for (int m = 0; m < 4; ++m) acc2[q][m] = 0ULL;

    int kkl = tid & 31;
    int hb = tid >> 5;

    for (int k0 = 0; k0 < 256; k0 += 32) {
        __syncthreads();
#pragma unroll
        for (int r = 0; r < 32; ++r) {
            int h = hb + r * 8;
            Ws[kkl * WST + h] = W[h * 256 + k0 + kkl];
        }
#pragma unroll
        for (int r = 0; r < 4; ++r) {
            int idx = r * 256 + tid;
            int tok = idx >> 5, kk = idx & 31;
            Xs[tok * 36 + kk] = X[(size_t)(tok0 + tok) * 256 + k0 + kk];
        }
        __syncthreads();
#pragma unroll 8
        for (int kk = 0; kk < 32; ++kk) {
            ull wv[4];
#pragma unroll
            for (int m = 0; m < 4; ++m)
                wv[m] = *(const ull*)(Ws + kk * WST + tx * 2 + 64 * m);
            ull xd[4];
#pragma unroll
            for (int q = 0; q < 4; ++q)
                xd[q] = pack_dup(Xs[(ty * 4 + q) * 36 + kk]);
#pragma unroll
            for (int q = 0; q < 4; ++q)
#pragma unroll
                for (int m = 0; m < 4; ++m)
                    fma2(acc2[q][m], xd[q], wv[m]);
        }
    }

    float e = which ? ba[0] : 0.0f;
    float part[4];
#pragma unroll
    for (int q = 0; q < 4; ++q) {
        float s = 0.0f;
#pragma unroll
        for (int m = 0; m < 4; ++m) {
            int h = tx * 2 + 64 * m;
            float a0, a1;
            unpack2(acc2[q][m], a0, a1);
            s += tanhf(a0 + bias_s[h]) * wa_s[h];
            s += tanhf(a1 + bias_s[h + 1]) * wa_s[h + 1];
        }
        part[q] = s;
    }
#pragma unroll
    for (int off = 16; off; off >>= 1) {
#pragma unroll
        for (int q = 0; q < 4; ++q)
            part[q] += __shfl_xor_sync(0xffffffffu, part[q], off);
    }
    if (tx == 0) {
        float* outp = which ? g_so : g_st;
#pragma unroll
        for (int q = 0; q < 4; ++q)
            outp[tok0 + ty * 4 + q] = part[q] + e;
    }
}

// ---------------------------------------------------------------------
// Kernel 2: attention with tf32 tensor-core PV (3xTF32 compensated).
// 256 threads, 64 rows/CTA. Warp (wm 0..3, wn 0..1): M-strip 16 rows,
// N-half 128 cols. P computed directly into A fragments (no smem P).
// V tile split into {hi,lo} tf32 float2 pairs in smem.
// ---------------------------------------------------------------------
#define ATTN_SMEM ((2 * JT * HH) * 4 + (JT * NP) * 8 + LL * 8 + LL * 4 + ROWS * 4)

__global__ __launch_bounds__(256, 1)
void k_attn(const float* __restrict__ V, float* __restrict__ out) {
    extern __shared__ float sm[];
    float*  raw   = sm;                          // 2*32*256 floats = 64 KB
    float2* Vsp   = (float2*)(raw + 2 * JT * HH);// 32*260 float2 = 66.6 KB
    float2* msom  = Vsp + JT * NP;               // 2048 float2 = 16 KB
    float*  base_s= (float*)(msom + LL);         // 8 KB
    float*  S_s   = base_s + LL;                 // 256 B

    int tid = threadIdx.x;
    int lane = tid & 31, wid = tid >> 5;
    int gid = lane >> 2, tig = lane & 3;
    int wm = wid & 3, wn = wid >> 2;             // wm 0..3 (M strip), wn 0..1 (N half)
    int b = blockIdx.x >> 5;
    int row0 = (blockIdx.x & 31) * ROWS;

    const float* Vg = V + (size_t)b * LL * HH;

    // prefetch tile 0 (32 j x 256 feat = 32 KB)
#pragma unroll
    for (int r = 0; r < 8; ++r) {
        int c = r * 256 + tid;
        cp16(raw + c * 4, Vg + c * 4);
    }
    asm volatile("cp.async.commit_group;\n");

    // preamble: base + msom tables
    const float* sog = g_so + b * LL;
    const float* mug = g_mult + b * LL;
    for (int i = tid; i < LL; i += 256) {
        base_s[i] = g_base[i];
        float m = mug[i];
        msom[i] = make_float2(m, sog[i] * m);
    }

    int lr0 = wm * 16 + gid;                     // local rows owned by this thread
    int i0 = row0 + lr0, i1 = i0 + 8;
    float st0 = g_st[b * LL + i0];
    float st1 = g_st[b * LL + i1];

    float acc[16][4];
#pragma unroll
    for (int nt = 0; nt < 16; ++nt)
#pragma unroll
        for (int q = 0; q < 4; ++q) acc[nt][q] = 0.0f;
    float sum0 = 0.0f, sum1 = 0.0f;

    for (int t = 0; t < NTT; ++t) {
        asm volatile("cp.async.wait_group 0;\n");
        __syncthreads();                         // raw[t&1] visible; prev compute done

        // ---- split pass: raw -> {hi,lo} tf32 pairs ----
        const float4* rsrc = (const float4*)(raw + (t & 1) * JT * HH);
#pragma unroll
        for (int r = 0; r < 8; ++r) {
            int idx4 = r * 256 + tid;            // float4 index, 0..2047
            int k = idx4 >> 6;                   // 64 float4 per row
            int n = (idx4 & 63) * 4;
            float4 v = rsrc[idx4];
            float2* dst = Vsp + k * NP + n;
            float vh0 = __uint_as_float(cvt_tf32(v.x));
            float vh1 = __uint_as_float(cvt_tf32(v.y));
            float vh2 = __uint_as_float(cvt_tf32(v.z));
            float vh3 = __uint_as_float(cvt_tf32(v.w));
            dst[0] = make_float2(vh0, __uint_as_float(cvt_tf32(v.x - vh0)));
            dst[1] = make_float2(vh1, __uint_as_float(cvt_tf32(v.y - vh1)));
            dst[2] = make_float2(vh2, __uint_as_float(cvt_tf32(v.z - vh2)));
            dst[3] = make_float2(vh3, __uint_as_float(cvt_tf32(v.w - vh3)));
        }

        // ---- prefetch next tile (overlaps compute) ----
        if (t + 1 < NTT) {
            float* rn = raw + ((t + 1) & 1) * JT * HH;
            const float* gs = Vg + (size_t)(t + 1) * JT * HH;
#pragma unroll
            for (int r = 0; r < 8; ++r) {
                int c = r * 256 + tid;
                cp16(rn + c * 4, gs + c * 4);
            }
            asm volatile("cp.async.commit_group;\n");
        }
        __syncthreads();                         // Vsp ready

        // ---- compute: 4 k-blocks of 8 ----
#pragma unroll
        for (int kb = 0; kb < 4; ++kb) {
            int jA = t * JT + kb * 8 + tig;      // cols tig, tig+4 of this k-block
            float2 q0 = msom[jA];
            float2 q1 = msom[jA + 4];
            int d00 = i0 - jA;       d00 = (d00 < 0) ? -d00 : d00;
            int d10 = i1 - jA;       d10 = (d10 < 0) ? -d10 : d10;
            int d01 = i0 - jA - 4;   d01 = (d01 < 0) ? -d01 : d01;
            int d11 = i1 - jA - 4;   d11 = (d11 < 0) ? -d11 : d11;
            float p00 = __expf(base_s[d00] * fmaf(st0, q0.x, q0.y)); // (i0, jA)
            float p10 = __expf(base_s[d10] * fmaf(st1, q0.x, q0.y)); // (i1, jA)
            float p01 = __expf(base_s[d01] * fmaf(st0, q1.x, q1.y)); // (i0, jA+4)
            float p11 = __expf(base_s[d11] * fmaf(st1, q1.x, q1.y)); // (i1, jA+4)
            sum0 += p00 + p01;
            sum1 += p10 + p11;
            // A fragments: a0=(i0,jA) a1=(i1,jA) a2=(i0,jA+4) a3=(i1,jA+4)
            unsigned a0h = cvt_tf32(p00), a1h = cvt_tf32(p10);
            unsigned a2h = cvt_tf32(p01), a3h = cvt_tf32(p11);
            unsigned a0l = cvt_tf32(p00 - __uint_as_float(a0h));
            unsigned a1l = cvt_tf32(p10 - __uint_as_float(a1h));
            unsigned a2l = cvt_tf32(p01 - __uint_as_float(a2h));
            unsigned a3l = cvt_tf32(p11 - __uint_as_float(a3h));

            const float2* B0 = Vsp + (kb * 8 + tig) * NP + wn * 128;     // k=tig row
            const float2* B1 = Vsp + (kb * 8 + tig + 4) * NP + wn * 128; // k=tig+4
#pragma unroll
            for (int nt = 0; nt < 16; ++nt) {
                float2 b0 = B0[nt * 8 + gid];    // {hi, lo} of V[k=tig][n]
                float2 b1 = B1[nt * 8 + gid];
                unsigned b0h = __float_as_uint(b0.x), b0l = __float_as_uint(b0.y);
                unsigned b1h = __float_as_uint(b1.x), b1l = __float_as_uint(b1.y);
                mma_tf32(acc[nt], a0h, a1h, a2h, a3h, b0h, b1h);  // hi*hi
                mma_tf32(acc[nt], a0l, a1l, a2l, a3l, b0h, b1h);  // lo*hi
                mma_tf32(acc[nt], a0h, a1h, a2h, a3h, b0l, b1l);  // hi*lo
            }
        }
    }

    // ---- row sums: reduce over the 4 lanes of each quad ----
    sum0 += __shfl_xor_sync(0xffffffffu, sum0, 1);
    sum0 += __shfl_xor_sync(0xffffffffu, sum0, 2);
    sum1 += __shfl_xor_sync(0xffffffffu, sum1, 1);
    sum1 += __shfl_xor_sync(0xffffffffu, sum1, 2);
    if (tig == 0 && wn == 0) {
        S_s[lr0] = sum0;
        S_s[lr0 + 8] = sum1;
    }
    __syncthreads();

    // ---- epilogue: normalize and store ----
    float inv0 = 1.0f / S_s[lr0];
    float inv1 = 1.0f / S_s[lr0 + 8];
    float* Ob = out + ((size_t)b * LL + row0) * HH;
#pragma unroll
    for (int nt = 0; nt < 16; ++nt) {
        int col = wn * 128 + nt * 8 + 2 * tig;
        *(float2*)(Ob + (size_t)lr0 * HH + col) =
            make_float2(acc[nt][0] * inv0, acc[nt][1] * inv0);
        *(float2*)(Ob + (size_t)(lr0 + 8) * HH + col) =
            make_float2(acc[nt][2] * inv1, acc[nt][3] * inv1);
    }
}

// ---------------------------------------------------------------------
extern "C" void kernel_launch(void* const* d_in, const int* in_sizes, int n_in,
                              void* d_out, int out_size) {
    const float* opinion = (const float*)d_in[0];
    const float* text    = (const float*)d_in[1];
    const int*   pos     = (const int*)d_in[2];
    const float* Wt      = (const float*)d_in[3];
    const float* bt      = (const float*)d_in[4];
    const float* Wo      = (const float*)d_in[5];
    const float* wa      = (const float*)d_in[6];
    const float* ba      = (const float*)d_in[7];
    float* out = (float*)d_out;

    cudaFuncSetAttribute(k_attn, cudaFuncAttributeMaxDynamicSharedMemorySize,
                         ATTN_SMEM);

    k_base_mult<<<(BB * LL + 255) / 256, 256>>>(pos);
    k_transform2<<<dim3(BB * LL / 32, 2), 256>>>(text, opinion, Wt, bt, Wo, wa, ba);
    k_attn<<<BB * (LL / ROWS), 256, ATTN_SMEM>>>(opinion, out);
}

// round 11
// speedup vs baseline: 2.8171x; 1.4629x over previous
#include <cuda_runtime.h>
#include <cstdint>
#include <cstddef>

#define BB 8
#define LL 2048
#define HH 256
#define ROWS 64
#define JT 32
#define NTT (LL / JT)     // 64 tiles
#define WST 258

typedef unsigned long long ull;

// -------- scratch (no allocations allowed: __device__ globals) --------
__device__ float g_base[LL];
__device__ float g_st[BB * LL];
__device__ float g_so[BB * LL];
__device__ float g_mult[BB * LL];

// ---------------------------------------------------------------------
// helpers
// ---------------------------------------------------------------------
__device__ __forceinline__ ull pack_dup(float p) {
    ull r;
    asm("mov.b64 %0, {%1, %1};" : "=l"(r) : "f"(p));
    return r;
}
__device__ __forceinline__ void fma2(ull& d, ull a, ull b) {
    asm("fma.rn.f32x2 %0, %1, %2, %0;" : "+l"(d) : "l"(a), "l"(b));
}
__device__ __forceinline__ void unpack2(ull v, float& lo, float& hi) {
    asm("mov.b64 {%0, %1}, %2;" : "=f"(lo), "=f"(hi) : "l"(v));
}
__device__ __forceinline__ unsigned cvt_tf32(float x) {
    unsigned r;
    asm("cvt.rna.tf32.f32 %0, %1;" : "=r"(r) : "f"(x));
    return r;
}
__device__ __forceinline__ void mma_tf32(float* c, unsigned a0, unsigned a1,
                                         unsigned a2, unsigned a3,
                                         unsigned b0, unsigned b1) {
    asm volatile(
        "mma.sync.aligned.m16n8k8.row.col.f32.tf32.tf32.f32 "
        "{%0,%1,%2,%3}, {%4,%5,%6,%7}, {%8,%9}, {%0,%1,%2,%3};"
        : "+f"(c[0]), "+f"(c[1]), "+f"(c[2]), "+f"(c[3])
        : "r"(a0), "r"(a1), "r"(a2), "r"(a3), "r"(b0), "r"(b1));
}
__device__ __forceinline__ void cp16(float* s, const float* g) {
    unsigned sa = (unsigned)__cvta_generic_to_shared(s);
    asm volatile("cp.async.cg.shared.global [%0], [%1], 16;\n" ::"r"(sa), "l"(g));
}

// ---------------------------------------------------------------------
// Kernel 0: base table + packed so/mult tables
// sop[j] = so_j with mantissa LSB = (mult==8); st kept separate.
// ---------------------------------------------------------------------
__global__ void k_base_mult(const int* __restrict__ pos) {
    int i = blockIdx.x * blockDim.x + threadIdx.x;
    if (i < LL) {
        g_base[i] = (i == 0) ? 0.5f : (1.0f / log2f(2.0f + (float)i));
    }
    if (i < BB * LL) {
        const unsigned long long mask =
            (1ULL << 19) | (1ULL << 20) | (1ULL << 21) |
            (1ULL << 33) | (1ULL << 34) | (1ULL << 35) |
            (1ULL << 41) | (1ULL << 42) | (1ULL << 43) |
            (1ULL << 44) | (1ULL << 45) | (1ULL << 46);
        int p = pos[i];
        bool op = (p >= 0) && (p < 64) && (((mask >> p) & 1ULL) != 0ULL);
        g_mult[i] = op ? 8.0f : 1.0f;
    }
}

// ---------------------------------------------------------------------
// Kernel 1: fused per-token transforms (y=0 -> st, y=1 -> so)
// ---------------------------------------------------------------------
__global__ __launch_bounds__(256)
void k_transform2(const float* __restrict__ text, const float* __restrict__ opinion,
                  const float* __restrict__ Wt, const float* __restrict__ bt,
                  const float* __restrict__ Wo, const float* __restrict__ wa,
                  const float* __restrict__ ba) {
    __shared__ float Ws[32 * WST];
    __shared__ float Xs[32 * 36];
    __shared__ float bias_s[256];
    __shared__ float wa_s[256];

    int which = blockIdx.y;
    const float* X = which ? opinion : text;
    const float* W = which ? Wo : Wt;
    const float* wav = which ? (wa + HH) : wa;

    int tid = threadIdx.x;
    int tx = tid & 31, ty = tid >> 5;
    int tok0 = blockIdx.x * 32;

    bias_s[tid] = which ? 0.0f : bt[tid];
    wa_s[tid] = wav[tid];

    ull acc2[4][4];
#pragma unroll
    for (int q = 0; q < 4; ++q)
#pragma unroll
        for (int m = 0; m < 4; ++m) acc2[q][m] = 0ULL;

    int kkl = tid & 31;
    int hb = tid >> 5;

    for (int k0 = 0; k0 < 256; k0 += 32) {
        __syncthreads();
#pragma unroll
        for (int r = 0; r < 32; ++r) {
            int h = hb + r * 8;
            Ws[kkl * WST + h] = W[h * 256 + k0 + kkl];
        }
#pragma unroll
        for (int r = 0; r < 4; ++r) {
            int idx = r * 256 + tid;
            int tok = idx >> 5, kk = idx & 31;
            Xs[tok * 36 + kk] = X[(size_t)(tok0 + tok) * 256 + k0 + kk];
        }
        __syncthreads();
#pragma unroll 8
        for (int kk = 0; kk < 32; ++kk) {
            ull wv[4];
#pragma unroll
            for (int m = 0; m < 4; ++m)
                wv[m] = *(const ull*)(Ws + kk * WST + tx * 2 + 64 * m);
            ull xd[4];
#pragma unroll
            for (int q = 0; q < 4; ++q)
                xd[q] = pack_dup(Xs[(ty * 4 + q) * 36 + kk]);
#pragma unroll
            for (int q = 0; q < 4; ++q)
#pragma unroll
                for (int m = 0; m < 4; ++m)
                    fma2(acc2[q][m], xd[q], wv[m]);
        }
    }

    float e = which ? ba[0] : 0.0f;
    float part[4];
#pragma unroll
    for (int q = 0; q < 4; ++q) {
        float s = 0.0f;
#pragma unroll
        for (int m = 0; m < 4; ++m) {
            int h = tx * 2 + 64 * m;
            float a0, a1;
            unpack2(acc2[q][m], a0, a1);
            s += tanhf(a0 + bias_s[h]) * wa_s[h];
            s += tanhf(a1 + bias_s[h + 1]) * wa_s[h + 1];
        }
        part[q] = s;
    }
#pragma unroll
    for (int off = 16; off; off >>= 1) {
#pragma unroll
        for (int q = 0; q < 4; ++q)
            part[q] += __shfl_xor_sync(0xffffffffu, part[q], off);
    }
    if (tx == 0) {
        float* outp = which ? g_so : g_st;
#pragma unroll
        for (int q = 0; q < 4; ++q)
            outp[tok0 + ty * 4 + q] = part[q] + e;
    }
}

// ---------------------------------------------------------------------
// Kernel 2: attention, tf32 tensor PV, 2-mma compensation (P exact,
// V hi-plane only). 2 CTAs/SM (112KB smem). XOR-swizzled V plane.
// ---------------------------------------------------------------------
#define NSW(k, n) ((k) * 256 + ((n) ^ (((k) & 3) * 8)))
#define ATTN_SMEM ((2 * JT * HH + JT * HH + LL + LL + ROWS) * 4)

__global__ __launch_bounds__(256, 2)
void k_attn(const float* __restrict__ V, float* __restrict__ out) {
    extern __shared__ float sm[];
    float* raw    = sm;                      // 2*32*256 = 16384 f (64 KB)
    float* Vsp    = raw + 2 * JT * HH;       // 32*256 = 8192 f (32 KB, swizzled)
    float* base_s = Vsp + JT * HH;           // 2048 f
    float* sop    = base_s + LL;             // 2048 f (so with mult bit in LSB)
    float* S_s    = sop + LL;                // 64 f

    int tid = threadIdx.x;
    int lane = tid & 31, wid = tid >> 5;
    int gid = lane >> 2, tig = lane & 3;
    int wm = wid & 3, wn = wid >> 2;         // M strip 16 rows, N half 128 cols
    int b = blockIdx.x >> 5;
    int row0 = (blockIdx.x & 31) * ROWS;

    const float* Vg = V + (size_t)b * LL * HH;

    // prefetch tile 0
#pragma unroll
    for (int r = 0; r < 8; ++r) {
        int c = r * 256 + tid;
        cp16(raw + c * 4, Vg + c * 4);
    }
    asm volatile("cp.async.commit_group;\n");

    // preamble tables
    const float* sog = g_so + b * LL;
    const float* mug = g_mult + b * LL;
    for (int i = tid; i < LL; i += 256) {
        base_s[i] = g_base[i];
        unsigned u = __float_as_uint(sog[i]);
        u = (u & ~1u) | (mug[i] > 4.0f ? 1u : 0u);
        sop[i] = __uint_as_float(u);
    }

    int lr0 = wm * 16 + gid;
    int i0 = row0 + lr0, i1 = i0 + 8;
    float st0 = g_st[b * LL + i0];
    float st1 = g_st[b * LL + i1];

    float acc[16][4];
#pragma unroll
    for (int nt = 0; nt < 16; ++nt)
#pragma unroll
        for (int q = 0; q < 4; ++q) acc[nt][q] = 0.0f;
    float sum0 = 0.0f, sum1 = 0.0f;

    for (int t = 0; t < NTT; ++t) {
        asm volatile("cp.async.wait_group 0;\n");
        __syncthreads();                     // raw[t&1] ready; Vsp free

        // ---- split pass: raw -> tf32 hi plane (swizzled) ----
        const float4* rsrc = (const float4*)(raw + (t & 1) * JT * HH);
#pragma unroll
        for (int r = 0; r < 8; ++r) {
            int idx4 = r * 256 + tid;
            int k = idx4 >> 6;
            int n4 = (idx4 & 63) * 4;
            float4 v = rsrc[idx4];
            float4 h;
            h.x = __uint_as_float(cvt_tf32(v.x));
            h.y = __uint_as_float(cvt_tf32(v.y));
            h.z = __uint_as_float(cvt_tf32(v.z));
            h.w = __uint_as_float(cvt_tf32(v.w));
            *(float4*)(Vsp + NSW(k, n4)) = h;
        }

        // ---- prefetch next tile ----
        if (t + 1 < NTT) {
            float* rn = raw + ((t + 1) & 1) * JT * HH;
            const float* gs = Vg + (size_t)(t + 1) * JT * HH;
#pragma unroll
            for (int r = 0; r < 8; ++r) {
                int c = r * 256 + tid;
                cp16(rn + c * 4, gs + c * 4);
            }
            asm volatile("cp.async.commit_group;\n");
        }
        __syncthreads();                     // Vsp ready

        // ---- compute: 4 k-blocks of 8 ----
#pragma unroll
        for (int kb = 0; kb < 4; ++kb) {
            int jA = t * JT + kb * 8 + tig;
            float q0 = sop[jA];
            float q1 = sop[jA + 4];
            float m0 = (__float_as_uint(q0) & 1u) ? 8.0f : 1.0f;
            float m1 = (__float_as_uint(q1) & 1u) ? 8.0f : 1.0f;
            int d00 = i0 - jA;     d00 = (d00 < 0) ? -d00 : d00;
            int d10 = i1 - jA;     d10 = (d10 < 0) ? -d10 : d10;
            int d01 = i0 - jA - 4; d01 = (d01 < 0) ? -d01 : d01;
            int d11 = i1 - jA - 4; d11 = (d11 < 0) ? -d11 : d11;
            float p00 = __expf(base_s[d00] * m0 * (st0 + q0));
            float p10 = __expf(base_s[d10] * m0 * (st1 + q0));
            float p01 = __expf(base_s[d01] * m1 * (st0 + q1));
            float p11 = __expf(base_s[d11] * m1 * (st1 + q1));
            sum0 += p00 + p01;
            sum1 += p10 + p11;
            unsigned a0h = cvt_tf32(p00), a1h = cvt_tf32(p10);
            unsigned a2h = cvt_tf32(p01), a3h = cvt_tf32(p11);
            unsigned a0l = cvt_tf32(p00 - __uint_as_float(a0h));
            unsigned a1l = cvt_tf32(p10 - __uint_as_float(a1h));
            unsigned a2l = cvt_tf32(p01 - __uint_as_float(a2h));
            unsigned a3l = cvt_tf32(p01 - __uint_as_float(a2h)); // placeholder
            a3l = cvt_tf32(p11 - __uint_as_float(a3h));

            int k0r = kb * 8 + tig;
            int k1r = k0r + 4;
            const float* B0 = Vsp + k0r * 256;
            const float* B1 = Vsp + k1r * 256;
            int xo = tig * 8;
#pragma unroll
            for (int nt = 0; nt < 16; ++nt) {
                int col = wn * 128 + nt * 8 + gid;
                unsigned b0h = __float_as_uint(B0[col ^ xo]);
                unsigned b1h = __float_as_uint(B1[col ^ xo]);
                mma_tf32(acc[nt], a0h, a1h, a2h, a3h, b0h, b1h);  // hi*hi
                mma_tf32(acc[nt], a0l, a1l, a2l, a3l, b0h, b1h);  // lo*hi
            }
        }
    }

    // ---- row sums ----
    sum0 += __shfl_xor_sync(0xffffffffu, sum0, 1);
    sum0 += __shfl_xor_sync(0xffffffffu, sum0, 2);
    sum1 += __shfl_xor_sync(0xffffffffu, sum1, 1);
    sum1 += __shfl_xor_sync(0xffffffffu, sum1, 2);
    if (tig == 0 && wn == 0) {
        S_s[lr0] = sum0;
        S_s[lr0 + 8] = sum1;
    }
    __syncthreads();

    // ---- epilogue ----
    float inv0 = 1.0f / S_s[lr0];
    float inv1 = 1.0f / S_s[lr0 + 8];
    float* Ob = out + ((size_t)b * LL + row0) * HH;
#pragma unroll
    for (int nt = 0; nt < 16; ++nt) {
        int col = wn * 128 + nt * 8 + 2 * tig;
        *(float2*)(Ob + (size_t)lr0 * HH + col) =
            make_float2(acc[nt][0] * inv0, acc[nt][1] * inv0);
        *(float2*)(Ob + (size_t)(lr0 + 8) * HH + col) =
            make_float2(acc[nt][2] * inv1, acc[nt][3] * inv1);
    }
}

// ---------------------------------------------------------------------
extern "C" void kernel_launch(void* const* d_in, const int* in_sizes, int n_in,
                              void* d_out, int out_size) {
    const float* opinion = (const float*)d_in[0];
    const float* text    = (const float*)d_in[1];
    const int*   pos     = (const int*)d_in[2];
    const float* Wt      = (const float*)d_in[3];
    const float* bt      = (const float*)d_in[4];
    const float* Wo      = (const float*)d_in[5];
    const float* wa      = (const float*)d_in[6];
    const float* ba      = (const float*)d_in[7];
    float* out = (float*)d_out;

    cudaFuncSetAttribute(k_attn, cudaFuncAttributeMaxDynamicSharedMemorySize,
                         ATTN_SMEM);

    k_base_mult<<<(BB * LL + 255) / 256, 256>>>(pos);
    k_transform2<<<dim3(BB * LL / 32, 2), 256>>>(text, opinion, Wt, bt, Wo, wa, ba);
    k_attn<<<BB * (LL / ROWS), 256, ATTN_SMEM>>>(opinion, out);
}

// round 13
// speedup vs baseline: 3.6610x; 1.2996x over previous
#include <cuda_runtime.h>
#include <cstdint>
#include <cstddef>

#define BB 8
#define LL 2048
#define HH 256
#define ROWS 64
#define JT 32
#define NTT (LL / JT)     // 64 tiles
#define WST 258

typedef unsigned long long ull;

// -------- scratch (no allocations allowed: __device__ globals) --------
__device__ float g_base[LL];
__device__ float g_st[BB * LL];
__device__ float g_so[BB * LL];
__device__ float g_mult[BB * LL];

// ---------------------------------------------------------------------
// helpers
// ---------------------------------------------------------------------
__device__ __forceinline__ ull pack_dup(float p) {
    ull r;
    asm("mov.b64 %0, {%1, %1};" : "=l"(r) : "f"(p));
    return r;
}
__device__ __forceinline__ void fma2(ull& d, ull a, ull b) {
    asm("fma.rn.f32x2 %0, %1, %2, %0;" : "+l"(d) : "l"(a), "l"(b));
}
__device__ __forceinline__ void unpack2(ull v, float& lo, float& hi) {
    asm("mov.b64 {%0, %1}, %2;" : "=f"(lo), "=f"(hi) : "l"(v));
}
__device__ __forceinline__ unsigned cvt_tf32(float x) {
    unsigned r;
    asm("cvt.rna.tf32.f32 %0, %1;" : "=r"(r) : "f"(x));
    return r;
}
__device__ __forceinline__ void mma_tf32(float* c, unsigned a0, unsigned a1,
                                         unsigned a2, unsigned a3,
                                         unsigned b0, unsigned b1) {
    asm volatile(
        "mma.sync.aligned.m16n8k8.row.col.f32.tf32.tf32.f32 "
        "{%0,%1,%2,%3}, {%4,%5,%6,%7}, {%8,%9}, {%0,%1,%2,%3};"
        : "+f"(c[0]), "+f"(c[1]), "+f"(c[2]), "+f"(c[3])
        : "r"(a0), "r"(a1), "r"(a2), "r"(a3), "r"(b0), "r"(b1));
}
__device__ __forceinline__ void cp16(float* s, const float* g) {
    unsigned sa = (unsigned)__cvta_generic_to_shared(s);
    asm volatile("cp.async.cg.shared.global [%0], [%1], 16;\n" ::"r"(sa), "l"(g));
}
// exp-based fast tanh: ~1e-6 abs error, ~6 instrs (vs ~20 for tanhf)
__device__ __forceinline__ float fast_tanh(float x) {
    float e = __expf(2.0f * x);
    return 1.0f - __fdividef(2.0f, e + 1.0f);
}

// ---------------------------------------------------------------------
// Kernel 0: base table + per-token column multiplier
// ---------------------------------------------------------------------
__global__ void k_base_mult(const int* __restrict__ pos) {
    int i = blockIdx.x * blockDim.x + threadIdx.x;
    if (i < LL) {
        g_base[i] = (i == 0) ? 0.5f : (1.0f / log2f(2.0f + (float)i));
    }
    if (i < BB * LL) {
        const unsigned long long mask =
            (1ULL << 19) | (1ULL << 20) | (1ULL << 21) |
            (1ULL << 33) | (1ULL << 34) | (1ULL << 35) |
            (1ULL << 41) | (1ULL << 42) | (1ULL << 43) |
            (1ULL << 44) | (1ULL << 45) | (1ULL << 46);
        int p = pos[i];
        bool op = (p >= 0) && (p < 64) && (((mask >> p) & 1ULL) != 0ULL);
        g_mult[i] = op ? 8.0f : 1.0f;
    }
}

// ---------------------------------------------------------------------
// Kernel 1: fused per-token transforms (y=0 -> st, y=1 -> so)
// ---------------------------------------------------------------------
__global__ __launch_bounds__(256)
void k_transform2(const float* __restrict__ text, const float* __restrict__ opinion,
                  const float* __restrict__ Wt, const float* __restrict__ bt,
                  const float* __restrict__ Wo, const float* __restrict__ wa,
                  const float* __restrict__ ba) {
    __shared__ float Ws[32 * WST];
    __shared__ float Xs[32 * 36];
    __shared__ float bias_s[256];
    __shared__ float wa_s[256];

    int which = blockIdx.y;
    const float* X = which ? opinion : text;
    const float* W = which ? Wo : Wt;
    const float* wav = which ? (wa + HH) : wa;

    int tid = threadIdx.x;
    int tx = tid & 31, ty = tid >> 5;
    int tok0 = blockIdx.x * 32;

    bias_s[tid] = which ? 0.0f : bt[tid];
    wa_s[tid] = wav[tid];

    ull acc2[4][4];
#pragma unroll
    for (int q = 0; q < 4; ++q)
#pragma unroll
        for (int m = 0; m < 4; ++m) acc2[q][m] = 0ULL;

    int kkl = tid & 31;
    int hb = tid >> 5;

    for (int k0 = 0; k0 < 256; k0 += 32) {
        __syncthreads();
#pragma unroll
        for (int r = 0; r < 32; ++r) {
            int h = hb + r * 8;
            Ws[kkl * WST + h] = W[h * 256 + k0 + kkl];
        }
#pragma unroll
        for (int r = 0; r < 4; ++r) {
            int idx = r * 256 + tid;
            int tok = idx >> 5, kk = idx & 31;
            Xs[tok * 36 + kk] = X[(size_t)(tok0 + tok) * 256 + k0 + kk];
        }
        __syncthreads();
#pragma unroll 8
        for (int kk = 0; kk < 32; ++kk) {
            ull wv[4];
#pragma unroll
            for (int m = 0; m < 4; ++m)
                wv[m] = *(const ull*)(Ws + kk * WST + tx * 2 + 64 * m);
            ull xd[4];
#pragma unroll
            for (int q = 0; q < 4; ++q)
                xd[q] = pack_dup(Xs[(ty * 4 + q) * 36 + kk]);
#pragma unroll
            for (int q = 0; q < 4; ++q)
#pragma unroll
                for (int m = 0; m < 4; ++m)
                    fma2(acc2[q][m], xd[q], wv[m]);
        }
    }

    float e = which ? ba[0] : 0.0f;
    float part[4];
#pragma unroll
    for (int q = 0; q < 4; ++q) {
        float s = 0.0f;
#pragma unroll
        for (int m = 0; m < 4; ++m) {
            int h = tx * 2 + 64 * m;
            float a0, a1;
            unpack2(acc2[q][m], a0, a1);
            s += fast_tanh(a0 + bias_s[h]) * wa_s[h];
            s += fast_tanh(a1 + bias_s[h + 1]) * wa_s[h + 1];
        }
        part[q] = s;
    }
#pragma unroll
    for (int off = 16; off; off >>= 1) {
#pragma unroll
        for (int q = 0; q < 4; ++q)
            part[q] += __shfl_xor_sync(0xffffffffu, part[q], off);
    }
    if (tx == 0) {
        float* outp = which ? g_so : g_st;
#pragma unroll
        for (int q = 0; q < 4; ++q)
            outp[tok0 + ty * 4 + q] = part[q] + e;
    }
}

// ---------------------------------------------------------------------
// Kernel 2: attention, tf32 tensor PV, single mma (P and V both tf32-rna).
// 2 CTAs/SM (112KB smem). XOR-swizzled V plane.
// ---------------------------------------------------------------------
#define NSW(k, n) ((k) * 256 + ((n) ^ (((k) & 3) * 8)))
#define ATTN_SMEM ((2 * JT * HH + JT * HH + LL + LL + ROWS) * 4)

__global__ __launch_bounds__(256, 2)
void k_attn(const float* __restrict__ V, float* __restrict__ out) {
    extern __shared__ float sm[];
    float* raw    = sm;                      // 2*32*256 = 16384 f (64 KB)
    float* Vsp    = raw + 2 * JT * HH;       // 32*256 = 8192 f (32 KB, swizzled)
    float* base_s = Vsp + JT * HH;           // 2048 f
    float* sop    = base_s + LL;             // 2048 f (so with mult bit in LSB)
    float* S_s    = sop + LL;                // 64 f

    int tid = threadIdx.x;
    int lane = tid & 31, wid = tid >> 5;
    int gid = lane >> 2, tig = lane & 3;
    int wm = wid & 3, wn = wid >> 2;         // M strip 16 rows, N half 128 cols
    int b = blockIdx.x >> 5;
    int row0 = (blockIdx.x & 31) * ROWS;

    const float* Vg = V + (size_t)b * LL * HH;

    // prefetch tile 0
#pragma unroll
    for (int r = 0; r < 8; ++r) {
        int c = r * 256 + tid;
        cp16(raw + c * 4, Vg + c * 4);
    }
    asm volatile("cp.async.commit_group;\n");

    // preamble tables
    const float* sog = g_so + b * LL;
    const float* mug = g_mult + b * LL;
    for (int i = tid; i < LL; i += 256) {
        base_s[i] = g_base[i];
        unsigned u = __float_as_uint(sog[i]);
        u = (u & ~1u) | (mug[i] > 4.0f ? 1u : 0u);
        sop[i] = __uint_as_float(u);
    }

    int lr0 = wm * 16 + gid;
    int i0 = row0 + lr0, i1 = i0 + 8;
    float st0 = g_st[b * LL + i0];
    float st1 = g_st[b * LL + i1];

    float acc[16][4];
#pragma unroll
    for (int nt = 0; nt < 16; ++nt)
#pragma unroll
        for (int q = 0; q < 4; ++q) acc[nt][q] = 0.0f;
    float sum0 = 0.0f, sum1 = 0.0f;

    for (int t = 0; t < NTT; ++t) {
        asm volatile("cp.async.wait_group 0;\n");
        __syncthreads();                     // raw[t&1] ready; Vsp free

        // ---- split pass: raw -> tf32 plane (rna, swizzled) ----
        const float4* rsrc = (const float4*)(raw + (t & 1) * JT * HH);
#pragma unroll
        for (int r = 0; r < 8; ++r) {
            int idx4 = r * 256 + tid;
            int k = idx4 >> 6;
            int n4 = (idx4 & 63) * 4;
            float4 v = rsrc[idx4];
            float4 h;
            h.x = __uint_as_float(cvt_tf32(v.x));
            h.y = __uint_as_float(cvt_tf32(v.y));
            h.z = __uint_as_float(cvt_tf32(v.z));
            h.w = __uint_as_float(cvt_tf32(v.w));
            *(float4*)(Vsp + NSW(k, n4)) = h;
        }

        // ---- prefetch next tile ----
        if (t + 1 < NTT) {
            float* rn = raw + ((t + 1) & 1) * JT * HH;
            const float* gs = Vg + (size_t)(t + 1) * JT * HH;
#pragma unroll
            for (int r = 0; r < 8; ++r) {
                int c = r * 256 + tid;
                cp16(rn + c * 4, gs + c * 4);
            }
            asm volatile("cp.async.commit_group;\n");
        }
        __syncthreads();                     // Vsp ready

        // ---- compute: 4 k-blocks of 8, single mma per nt ----
#pragma unroll
        for (int kb = 0; kb < 4; ++kb) {
            int jA = t * JT + kb * 8 + tig;
            float q0 = sop[jA];
            float q1 = sop[jA + 4];
            float m0 = (__float_as_uint(q0) & 1u) ? 8.0f : 1.0f;
            float m1 = (__float_as_uint(q1) & 1u) ? 8.0f : 1.0f;
            int d00 = i0 - jA;     d00 = (d00 < 0) ? -d00 : d00;
            int d10 = i1 - jA;     d10 = (d10 < 0) ? -d10 : d10;
            int d01 = i0 - jA - 4; d01 = (d01 < 0) ? -d01 : d01;
            int d11 = i1 - jA - 4; d11 = (d11 < 0) ? -d11 : d11;
            float p00 = __expf(base_s[d00] * m0 * (st0 + q0));
            float p10 = __expf(base_s[d10] * m0 * (st1 + q0));
            float p01 = __expf(base_s[d01] * m1 * (st0 + q1));
            float p11 = __expf(base_s[d11] * m1 * (st1 + q1));
            sum0 += p00 + p01;
            sum1 += p10 + p11;
            unsigned a0h = cvt_tf32(p00), a1h = cvt_tf32(p10);
            unsigned a2h = cvt_tf32(p01), a3h = cvt_tf32(p11);

            int k0r = kb * 8 + tig;
            int k1r = k0r + 4;
            const float* B0 = Vsp + k0r * 256;
            const float* B1 = Vsp + k1r * 256;
            int xo = tig * 8;
#pragma unroll
            for (int nt = 0; nt < 16; ++nt) {
                int col = wn * 128 + nt * 8 + gid;
                unsigned b0h = __float_as_uint(B0[col ^ xo]);
                unsigned b1h = __float_as_uint(B1[col ^ xo]);
                mma_tf32(acc[nt], a0h, a1h, a2h, a3h, b0h, b1h);
            }
        }
    }

    // ---- row sums ----
    sum0 += __shfl_xor_sync(0xffffffffu, sum0, 1);
    sum0 += __shfl_xor_sync(0xffffffffu, sum0, 2);
    sum1 += __shfl_xor_sync(0xffffffffu, sum1, 1);
    sum1 += __shfl_xor_sync(0xffffffffu, sum1, 2);
    if (tig == 0 && wn == 0) {
        S_s[lr0] = sum0;
        S_s[lr0 + 8] = sum1;
    }
    __syncthreads();

    // ---- epilogue ----
    float inv0 = 1.0f / S_s[lr0];
    float inv1 = 1.0f / S_s[lr0 + 8];
    float* Ob = out + ((size_t)b * LL + row0) * HH;
#pragma unroll
    for (int nt = 0; nt < 16; ++nt) {
        int col = wn * 128 + nt * 8 + 2 * tig;
        *(float2*)(Ob + (size_t)lr0 * HH + col) =
            make_float2(acc[nt][0] * inv0, acc[nt][1] * inv0);
        *(float2*)(Ob + (size_t)(lr0 + 8) * HH + col) =
            make_float2(acc[nt][2] * inv1, acc[nt][3] * inv1);
    }
}

// ---------------------------------------------------------------------
extern "C" void kernel_launch(void* const* d_in, const int* in_sizes, int n_in,
                              void* d_out, int out_size) {
    const float* opinion = (const float*)d_in[0];
    const float* text    = (const float*)d_in[1];
    const int*   pos     = (const int*)d_in[2];
    const float* Wt      = (const float*)d_in[3];
    const float* bt      = (const float*)d_in[4];
    const float* Wo      = (const float*)d_in[5];
    const float* wa      = (const float*)d_in[6];
    const float* ba      = (const float*)d_in[7];
    float* out = (float*)d_out;

    cudaFuncSetAttribute(k_attn, cudaFuncAttributeMaxDynamicSharedMemorySize,
                         ATTN_SMEM);

    k_base_mult<<<(BB * LL + 255) / 256, 256>>>(pos);
    k_transform2<<<dim3(BB * LL / 32, 2), 256>>>(text, opinion, Wt, bt, Wo, wa, ba);
    k_attn<<<BB * (LL / ROWS), 256, ATTN_SMEM>>>(opinion, out);
}

// round 14
// speedup vs baseline: 3.8892x; 1.0624x over previous
#include <cuda_runtime.h>
#include <cstdint>
#include <cstddef>

#define BB 8
#define LL 2048
#define HH 256
#define ROWS 64
#define JT 32
#define NTT (LL / JT)     // 64 tiles
#define WST 258

typedef unsigned long long ull;

// -------- scratch (no allocations allowed: __device__ globals) --------
__device__ float g_base[LL];
__device__ float g_st[BB * LL];
__device__ float g_so[BB * LL];
__device__ float g_mult[BB * LL];
// pre-converted tf32 V, k-pair interleaved + bank-swizzled smem image:
// g_v2[((b*64+t)*16 + pair)*256 + c] = {V[k][n], V[k+4][n]},
//   pair = kb*4+tig, k = t*32+kb*8+tig, c = n ^ (tig*4)
__device__ float2 g_v2[BB * NTT * 16 * 256];   // 16.8 MB

// ---------------------------------------------------------------------
// helpers
// ---------------------------------------------------------------------
__device__ __forceinline__ ull pack_dup(float p) {
    ull r;
    asm("mov.b64 %0, {%1, %1};" : "=l"(r) : "f"(p));
    return r;
}
__device__ __forceinline__ void fma2(ull& d, ull a, ull b) {
    asm("fma.rn.f32x2 %0, %1, %2, %0;" : "+l"(d) : "l"(a), "l"(b));
}
__device__ __forceinline__ void unpack2(ull v, float& lo, float& hi) {
    asm("mov.b64 {%0, %1}, %2;" : "=f"(lo), "=f"(hi) : "l"(v));
}
__device__ __forceinline__ unsigned cvt_tf32(float x) {
    unsigned r;
    asm("cvt.rna.tf32.f32 %0, %1;" : "=r"(r) : "f"(x));
    return r;
}
__device__ __forceinline__ void mma_tf32(float* c, unsigned a0, unsigned a1,
                                         unsigned a2, unsigned a3,
                                         unsigned b0, unsigned b1) {
    asm volatile(
        "mma.sync.aligned.m16n8k8.row.col.f32.tf32.tf32.f32 "
        "{%0,%1,%2,%3}, {%4,%5,%6,%7}, {%8,%9}, {%0,%1,%2,%3};"
        : "+f"(c[0]), "+f"(c[1]), "+f"(c[2]), "+f"(c[3])
        : "r"(a0), "r"(a1), "r"(a2), "r"(a3), "r"(b0), "r"(b1));
}
__device__ __forceinline__ void cp16(void* s, const void* g) {
    unsigned sa = (unsigned)__cvta_generic_to_shared(s);
    asm volatile("cp.async.cg.shared.global [%0], [%1], 16;\n" ::"r"(sa), "l"(g));
}
__device__ __forceinline__ float fast_tanh(float x) {
    float e = __expf(2.0f * x);
    return 1.0f - __fdividef(2.0f, e + 1.0f);
}

// ---------------------------------------------------------------------
// Kernel 0: base table + per-token column multiplier
// ---------------------------------------------------------------------
__global__ void k_base_mult(const int* __restrict__ pos) {
    int i = blockIdx.x * blockDim.x + threadIdx.x;
    if (i < LL) {
        g_base[i] = (i == 0) ? 0.5f : (1.0f / log2f(2.0f + (float)i));
    }
    if (i < BB * LL) {
        const unsigned long long mask =
            (1ULL << 19) | (1ULL << 20) | (1ULL << 21) |
            (1ULL << 33) | (1ULL << 34) | (1ULL << 35) |
            (1ULL << 41) | (1ULL << 42) | (1ULL << 43) |
            (1ULL << 44) | (1ULL << 45) | (1ULL << 46);
        int p = pos[i];
        bool op = (p >= 0) && (p < 64) && (((mask >> p) & 1ULL) != 0ULL);
        g_mult[i] = op ? 8.0f : 1.0f;
    }
}

// ---------------------------------------------------------------------
// Kernel 0b: V -> tf32, pair-interleaved + swizzled smem image (runs once)
// ---------------------------------------------------------------------
__global__ __launch_bounds__(256)
void k_v2(const float* __restrict__ V) {
    int bt = blockIdx.x;                 // b*64 + t
    int b = bt >> 6, t = bt & 63;
    const float* Vb = V + (size_t)b * LL * HH;
    float2* outp = g_v2 + (size_t)bt * 4096;
#pragma unroll
    for (int it = 0; it < 16; ++it) {
        int idx = it * 256 + threadIdx.x;    // 0..4095
        int p = idx >> 8, c = idx & 255;
        int tig = p & 3;
        int n = c ^ (tig * 4);
        int k = t * 32 + (p >> 2) * 8 + tig;
        float2 o;
        o.x = __uint_as_float(cvt_tf32(Vb[(size_t)k * HH + n]));
        o.y = __uint_as_float(cvt_tf32(Vb[(size_t)(k + 4) * HH + n]));
        outp[idx] = o;
    }
}

// ---------------------------------------------------------------------
// Kernel 1: fused per-token transforms (y=0 -> st, y=1 -> so)
// ---------------------------------------------------------------------
__global__ __launch_bounds__(256)
void k_transform2(const float* __restrict__ text, const float* __restrict__ opinion,
                  const float* __restrict__ Wt, const float* __restrict__ bt,
                  const float* __restrict__ Wo, const float* __restrict__ wa,
                  const float* __restrict__ ba) {
    __shared__ float Ws[32 * WST];
    __shared__ float Xs[32 * 36];
    __shared__ float bias_s[256];
    __shared__ float wa_s[256];

    int which = blockIdx.y;
    const float* X = which ? opinion : text;
    const float* W = which ? Wo : Wt;
    const float* wav = which ? (wa + HH) : wa;

    int tid = threadIdx.x;
    int tx = tid & 31, ty = tid >> 5;
    int tok0 = blockIdx.x * 32;

    bias_s[tid] = which ? 0.0f : bt[tid];
    wa_s[tid] = wav[tid];

    ull acc2[4][4];
#pragma unroll
    for (int q = 0; q < 4; ++q)
#pragma unroll
        for (int m = 0; m < 4; ++m) acc2[q][m] = 0ULL;

    int kkl = tid & 31;
    int hb = tid >> 5;

    for (int k0 = 0; k0 < 256; k0 += 32) {
        __syncthreads();
#pragma unroll
        for (int r = 0; r < 32; ++r) {
            int h = hb + r * 8;
            Ws[kkl * WST + h] = W[h * 256 + k0 + kkl];
        }
#pragma unroll
        for (int r = 0; r < 4; ++r) {
            int idx = r * 256 + tid;
            int tok = idx >> 5, kk = idx & 31;
            Xs[tok * 36 + kk] = X[(size_t)(tok0 + tok) * 256 + k0 + kk];
        }
        __syncthreads();
#pragma unroll 8
        for (int kk = 0; kk < 32; ++kk) {
            ull wv[4];
#pragma unroll
            for (int m = 0; m < 4; ++m)
                wv[m] = *(const ull*)(Ws + kk * WST + tx * 2 + 64 * m);
            ull xd[4];
#pragma unroll
            for (int q = 0; q < 4; ++q)
                xd[q] = pack_dup(Xs[(ty * 4 + q) * 36 + kk]);
#pragma unroll
            for (int q = 0; q < 4; ++q)
#pragma unroll
                for (int m = 0; m < 4; ++m)
                    fma2(acc2[q][m], xd[q], wv[m]);
        }
    }

    float e = which ? ba[0] : 0.0f;
    float part[4];
#pragma unroll
    for (int q = 0; q < 4; ++q) {
        float s = 0.0f;
#pragma unroll
        for (int m = 0; m < 4; ++m) {
            int h = tx * 2 + 64 * m;
            float a0, a1;
            unpack2(acc2[q][m], a0, a1);
            s += fast_tanh(a0 + bias_s[h]) * wa_s[h];
            s += fast_tanh(a1 + bias_s[h + 1]) * wa_s[h + 1];
        }
        part[q] = s;
    }
#pragma unroll
    for (int off = 16; off; off >>= 1) {
#pragma unroll
        for (int q = 0; q < 4; ++q)
            part[q] += __shfl_xor_sync(0xffffffffu, part[q], off);
    }
    if (tx == 0) {
        float* outp = which ? g_so : g_st;
#pragma unroll
        for (int q = 0; q < 4; ++q)
            outp[tok0 + ty * 4 + q] = part[q] + e;
    }
}

// ---------------------------------------------------------------------
// Kernel 2: attention, tf32 tensor PV, single mma. V arrives via identity
// cp.async from pre-swizzled g_v2 (no split pass). LDS.64 B fragments.
// 2 CTAs/SM (82 KB smem).
// ---------------------------------------------------------------------
#define ATTN_SMEM (2 * 4096 * 8 + LL * 4 + LL * 4 + ROWS * 4)

__global__ __launch_bounds__(256, 2)
void k_attn(float* __restrict__ out) {
    extern __shared__ float sm[];
    float2* Vd    = (float2*)sm;             // 2 * 4096 float2 = 64 KB
    float*  base_s= (float*)(Vd + 2 * 4096); // 2048 f
    float*  sop   = base_s + LL;             // 2048 f (so with mult bit in LSB)
    float*  S_s   = sop + LL;                // 64 f

    int tid = threadIdx.x;
    int lane = tid & 31, wid = tid >> 5;
    int gid = lane >> 2, tig = lane & 3;
    int wm = wid & 3, wn = wid >> 2;         // M strip 16 rows, N half 128 cols
    int b = blockIdx.x >> 5;
    int row0 = (blockIdx.x & 31) * ROWS;

    const float2* V2g = g_v2 + (size_t)b * NTT * 4096;

    // prefetch tile 0 (identity copy: 4096 float2 = 32 KB)
#pragma unroll
    for (int r = 0; r < 8; ++r) {
        int chunk = r * 256 + tid;           // 16B chunks, 0..2047
        cp16(Vd + chunk * 2, V2g + chunk * 2);
    }
    asm volatile("cp.async.commit_group;\n");

    // preamble tables
    const float* sog = g_so + b * LL;
    const float* mug = g_mult + b * LL;
    for (int i = tid; i < LL; i += 256) {
        base_s[i] = g_base[i];
        unsigned u = __float_as_uint(sog[i]);
        u = (u & ~1u) | (mug[i] > 4.0f ? 1u : 0u);
        sop[i] = __uint_as_float(u);
    }

    int lr0 = wm * 16 + gid;
    int i0 = row0 + lr0, i1 = i0 + 8;
    float st0 = g_st[b * LL + i0];
    float st1 = g_st[b * LL + i1];

    float acc[16][4];
#pragma unroll
    for (int nt = 0; nt < 16; ++nt)
#pragma unroll
        for (int q = 0; q < 4; ++q) acc[nt][q] = 0.0f;
    float sum0 = 0.0f, sum1 = 0.0f;

    for (int t = 0; t < NTT; ++t) {
        asm volatile("cp.async.wait_group 0;\n");  // my fill(t) chunks landed
        __syncthreads();                           // all landed; other buf free

        // ---- prefetch next tile ----
        if (t + 1 < NTT) {
            float2* dn = Vd + ((t + 1) & 1) * 4096;
            const float2* gs = V2g + (size_t)(t + 1) * 4096;
#pragma unroll
            for (int r = 0; r < 8; ++r) {
                int chunk = r * 256 + tid;
                cp16(dn + chunk * 2, gs + chunk * 2);
            }
            asm volatile("cp.async.commit_group;\n");
        }

        // ---- compute on buffer t&1 ----
        const float2* Vb2 = Vd + (t & 1) * 4096;
#pragma unroll
        for (int kb = 0; kb < 4; ++kb) {
            int jA = t * JT + kb * 8 + tig;
            float q0 = sop[jA];
            float q1 = sop[jA + 4];
            float m0 = (__float_as_uint(q0) & 1u) ? 8.0f : 1.0f;
            float m1 = (__float_as_uint(q1) & 1u) ? 8.0f : 1.0f;
            int d00 = i0 - jA;     d00 = (d00 < 0) ? -d00 : d00;
            int d10 = i1 - jA;     d10 = (d10 < 0) ? -d10 : d10;
            int d01 = i0 - jA - 4; d01 = (d01 < 0) ? -d01 : d01;
            int d11 = i1 - jA - 4; d11 = (d11 < 0) ? -d11 : d11;
            float p00 = __expf(base_s[d00] * m0 * (st0 + q0));
            float p10 = __expf(base_s[d10] * m0 * (st1 + q0));
            float p01 = __expf(base_s[d01] * m1 * (st0 + q1));
            float p11 = __expf(base_s[d11] * m1 * (st1 + q1));
            sum0 += p00 + p01;
            sum1 += p10 + p11;
            unsigned a0h = cvt_tf32(p00), a1h = cvt_tf32(p10);
            unsigned a2h = cvt_tf32(p01), a3h = cvt_tf32(p11);

            // B pairs: {V[k][col], V[k+4][col]} at c = col ^ (tig*4)
            const float2* Bp = Vb2 + (kb * 4 + tig) * 256 + wn * 128;
            int cx = gid ^ (tig * 4);      // col ^ swz, gid part
#pragma unroll
            for (int nt = 0; nt < 16; ++nt) {
                float2 bb = Bp[(nt * 8) ^ cx];   // nt*8 has no bits 0-2; XOR ok
                mma_tf32(acc[nt], a0h, a1h, a2h, a3h,
                         __float_as_uint(bb.x), __float_as_uint(bb.y));
            }
        }
        __syncthreads();   // compute(t) done before fill(t+2) overwrites? (2-buf: fill(t+1) already issued into other buf; this sync protects buf t&1 for fill at t+2 issued next iter)
    }

    // ---- row sums ----
    sum0 += __shfl_xor_sync(0xffffffffu, sum0, 1);
    sum0 += __shfl_xor_sync(0xffffffffu, sum0, 2);
    sum1 += __shfl_xor_sync(0xffffffffu, sum1, 1);
    sum1 += __shfl_xor_sync(0xffffffffu, sum1, 2);
    if (tig == 0 && wn == 0) {
        S_s[lr0] = sum0;
        S_s[lr0 + 8] = sum1;
    }
    __syncthreads();

    // ---- epilogue ----
    float inv0 = 1.0f / S_s[lr0];
    float inv1 = 1.0f / S_s[lr0 + 8];
    float* Ob = out + ((size_t)b * LL + row0) * HH;
#pragma unroll
    for (int nt = 0; nt < 16; ++nt) {
        int col = wn * 128 + nt * 8 + 2 * tig;
        *(float2*)(Ob + (size_t)lr0 * HH + col) =
            make_float2(acc[nt][0] * inv0, acc[nt][1] * inv0);
        *(float2*)(Ob + (size_t)(lr0 + 8) * HH + col) =
            make_float2(acc[nt][2] * inv1, acc[nt][3] * inv1);
    }
}

// ---------------------------------------------------------------------
extern "C" void kernel_launch(void* const* d_in, const int* in_sizes, int n_in,
                              void* d_out, int out_size) {
    const float* opinion = (const float*)d_in[0];
    const float* text    = (const float*)d_in[1];
    const int*   pos     = (const int*)d_in[2];
    const float* Wt      = (const float*)d_in[3];
    const float* bt      = (const float*)d_in[4];
    const float* Wo      = (const float*)d_in[5];
    const float* wa      = (const float*)d_in[6];
    const float* ba      = (const float*)d_in[7];
    float* out = (float*)d_out;

    cudaFuncSetAttribute(k_attn, cudaFuncAttributeMaxDynamicSharedMemorySize,
                         ATTN_SMEM);

    k_base_mult<<<(BB * LL + 255) / 256, 256>>>(pos);
    k_v2<<<BB * NTT, 256>>>(opinion);
    k_transform2<<<dim3(BB * LL / 32, 2), 256>>>(text, opinion, Wt, bt, Wo, wa, ba);
    k_attn<<<BB * (LL / ROWS), 256, ATTN_SMEM>>>(out);
}

// round 15
// speedup vs baseline: 4.7695x; 1.2263x over previous
#include <cuda_runtime.h>
#include <cstdint>
#include <cstddef>

#define BB 8
#define LL 2048
#define HH 256
#define ROWS 64
#define JT 32
#define NTT (LL / JT)     // 64 tiles

typedef unsigned long long ull;

// -------- scratch (no allocations allowed: __device__ globals) --------
__device__ float g_base[LL];
__device__ float g_st[BB * LL];
__device__ float g_so[BB * LL];
__device__ float g_mult[BB * LL];
// pre-converted tf32 V, k-pair interleaved + bank-swizzled smem image:
// g_v2[((b*64+t)*16 + pair)*256 + c] = {V[k][n], V[k+4][n]},
//   pair = kb*4+tig, k = t*32+kb*8+tig, c = n ^ (tig*4)
__device__ float2 g_v2[BB * NTT * 16 * 256];   // 16.8 MB
// pre-converted W images (hi+lo planes packed in float4):
// g_w2[((which*8+kt)*16 + pair)*256 + c] = {Whi[n][k], Whi[n][k+4],
//                                           Wlo[n][k], Wlo[n][k+4]},
//   pair = kb*4+tig, k = kt*32+kb*8+tig, n = c ^ (tig*2)
__device__ float4 g_w2[2 * 8 * 16 * 256];      // 1 MB

// ---------------------------------------------------------------------
// helpers
// ---------------------------------------------------------------------
__device__ __forceinline__ unsigned cvt_tf32(float x) {
    unsigned r;
    asm("cvt.rna.tf32.f32 %0, %1;" : "=r"(r) : "f"(x));
    return r;
}
__device__ __forceinline__ void mma_tf32(float* c, unsigned a0, unsigned a1,
                                         unsigned a2, unsigned a3,
                                         unsigned b0, unsigned b1) {
    asm volatile(
        "mma.sync.aligned.m16n8k8.row.col.f32.tf32.tf32.f32 "
        "{%0,%1,%2,%3}, {%4,%5,%6,%7}, {%8,%9}, {%0,%1,%2,%3};"
        : "+f"(c[0]), "+f"(c[1]), "+f"(c[2]), "+f"(c[3])
        : "r"(a0), "r"(a1), "r"(a2), "r"(a3), "r"(b0), "r"(b1));
}
__device__ __forceinline__ void cp16(void* s, const void* g) {
    unsigned sa = (unsigned)__cvta_generic_to_shared(s);
    asm volatile("cp.async.cg.shared.global [%0], [%1], 16;\n" ::"r"(sa), "l"(g));
}
__device__ __forceinline__ float fast_tanh(float x) {
    float e = __expf(2.0f * x);
    return 1.0f - __fdividef(2.0f, e + 1.0f);
}

// ---------------------------------------------------------------------
// Kernel 0: base table + per-token column multiplier
// ---------------------------------------------------------------------
__global__ void k_base_mult(const int* __restrict__ pos) {
    int i = blockIdx.x * blockDim.x + threadIdx.x;
    if (i < LL) {
        g_base[i] = (i == 0) ? 0.5f : (1.0f / log2f(2.0f + (float)i));
    }
    if (i < BB * LL) {
        const unsigned long long mask =
            (1ULL << 19) | (1ULL << 20) | (1ULL << 21) |
            (1ULL << 33) | (1ULL << 34) | (1ULL << 35) |
            (1ULL << 41) | (1ULL << 42) | (1ULL << 43) |
            (1ULL << 44) | (1ULL << 45) | (1ULL << 46);
        int p = pos[i];
        bool op = (p >= 0) && (p < 64) && (((mask >> p) & 1ULL) != 0ULL);
        g_mult[i] = op ? 8.0f : 1.0f;
    }
}

// ---------------------------------------------------------------------
// Kernel 0b: V -> tf32 pair image (runs once)
// ---------------------------------------------------------------------
__global__ __launch_bounds__(256)
void k_v2(const float* __restrict__ V) {
    int bt = blockIdx.x;                 // b*64 + t
    int b = bt >> 6, t = bt & 63;
    const float* Vb = V + (size_t)b * LL * HH;
    float2* outp = g_v2 + (size_t)bt * 4096;
#pragma unroll
    for (int it = 0; it < 16; ++it) {
        int idx = it * 256 + threadIdx.x;    // 0..4095
        int p = idx >> 8, c = idx & 255;
        int tig = p & 3;
        int n = c ^ (tig * 4);
        int k = t * 32 + (p >> 2) * 8 + tig;
        float2 o;
        o.x = __uint_as_float(cvt_tf32(Vb[(size_t)k * HH + n]));
        o.y = __uint_as_float(cvt_tf32(Vb[(size_t)(k + 4) * HH + n]));
        outp[idx] = o;
    }
}

// ---------------------------------------------------------------------
// Kernel 0c: W -> tf32 hi/lo pair image (runs once; tiny)
// ---------------------------------------------------------------------
__global__ __launch_bounds__(256)
void k_w2(const float* __restrict__ Wt, const float* __restrict__ Wo) {
    int which = blockIdx.x >> 3, kt = blockIdx.x & 7;
    const float* W = which ? Wo : Wt;
    float4* outp = g_w2 + (size_t)(which * 8 + kt) * 4096;
#pragma unroll
    for (int it = 0; it < 16; ++it) {
        int idx = it * 256 + threadIdx.x;    // 0..4095
        int p = idx >> 8, c = idx & 255;
        int tig = p & 3;
        int n = c ^ (tig * 2);
        int k = kt * 32 + (p >> 2) * 8 + tig;
        float w0 = W[n * 256 + k];
        float w1 = W[n * 256 + k + 4];
        float h0 = __uint_as_float(cvt_tf32(w0));
        float h1 = __uint_as_float(cvt_tf32(w1));
        float4 o;
        o.x = h0;
        o.y = h1;
        o.z = __uint_as_float(cvt_tf32(w0 - h0));
        o.w = __uint_as_float(cvt_tf32(w1 - h1));
        outp[idx] = o;
    }
}

// ---------------------------------------------------------------------
// Kernel 1: per-token transform via tf32 mma (2-mma: Xhi x (Whi+Wlo)).
// CTA = 64 tokens x 256 h; warps wm(4) x wn(2); K = 8 k-tiles of 32.
// Epilogue: st/so = sum_h fast_tanh(t_h + bias_h) * wa_h  (+ba).
// ---------------------------------------------------------------------
#define TR_SMEM (4096 * 16 + 64 * 36 * 4 + 256 * 4 + 256 * 4 + 128 * 4)

__global__ __launch_bounds__(256, 2)
void k_transform_mma(const float* __restrict__ text, const float* __restrict__ opinion,
                     const float* __restrict__ bt, const float* __restrict__ wa,
                     const float* __restrict__ ba) {
    extern __shared__ float sm[];
    float4* Wc     = (float4*)sm;            // 4096 float4 = 64 KB
    float*  Xs     = (float*)(Wc + 4096);    // 64*36 = 2304 f (9216 B)
    float*  bias_s = Xs + 64 * 36;           // 256 f
    float*  wa_s   = bias_s + 256;           // 256 f
    float*  red    = wa_s + 256;             // 128 f

    int which = blockIdx.y;
    const float* X = which ? opinion : text;
    const float* wav = which ? (wa + HH) : wa;

    int tid = threadIdx.x;
    int lane = tid & 31, wid = tid >> 5;
    int gid = lane >> 2, tig = lane & 3;
    int wm = wid & 3, wn = wid >> 2;
    int tok0 = blockIdx.x * 64;

    bias_s[tid] = which ? 0.0f : bt[tid];
    wa_s[tid] = wav[tid];

    int r0 = wm * 16 + gid;                  // local token rows r0, r0+8
    const float4* Wg = g_w2 + (size_t)which * 8 * 4096;

    float acc[16][4];
#pragma unroll
    for (int nt = 0; nt < 16; ++nt)
#pragma unroll
        for (int q = 0; q < 4; ++q) acc[nt][q] = 0.0f;

    for (int kt = 0; kt < 8; ++kt) {
        if (kt) __syncthreads();             // Wc/Xs consumed
        // W chunk: identity copy of 4096 float4
        const float4* ws = Wg + kt * 4096;
#pragma unroll
        for (int r = 0; r < 16; ++r) {
            int idx = r * 256 + tid;
            cp16(Wc + idx, ws + idx);
        }
        // X chunk: 64 rows x 32 k (fp32), 8 16B-chunks per row
#pragma unroll
        for (int r = 0; r < 2; ++r) {
            int ch = r * 256 + tid;          // 0..511
            int row = ch >> 3, c4 = (ch & 7) * 4;
            cp16(Xs + row * 36 + c4, X + (size_t)(tok0 + row) * 256 + kt * 32 + c4);
        }
        asm volatile("cp.async.commit_group;\n");
        asm volatile("cp.async.wait_group 0;\n");
        __syncthreads();

#pragma unroll
        for (int kb = 0; kb < 4; ++kb) {
            int kk = kb * 8 + tig;
            float x0 = Xs[r0 * 36 + kk];
            float x1 = Xs[(r0 + 8) * 36 + kk];
            float x2 = Xs[r0 * 36 + kk + 4];
            float x3 = Xs[(r0 + 8) * 36 + kk + 4];
            unsigned a0 = cvt_tf32(x0), a1 = cvt_tf32(x1);
            unsigned a2 = cvt_tf32(x2), a3 = cvt_tf32(x3);

            const float4* Bq = Wc + (kb * 4 + tig) * 256 + wn * 128;
            int cx = gid ^ (tig * 2);
#pragma unroll
            for (int nt = 0; nt < 16; ++nt) {
                float4 w4 = Bq[(nt * 8) ^ cx];
                mma_tf32(acc[nt], a0, a1, a2, a3,
                         __float_as_uint(w4.x), __float_as_uint(w4.y));
                mma_tf32(acc[nt], a0, a1, a2, a3,
                         __float_as_uint(w4.z), __float_as_uint(w4.w));
            }
        }
    }

    // ---- epilogue: tanh dot wa, reduce ----
    float p0 = 0.0f, p1 = 0.0f;
#pragma unroll
    for (int nt = 0; nt < 16; ++nt) {
        int col0 = wn * 128 + nt * 8 + 2 * tig;
        int col1 = col0 + 1;
        float b0 = bias_s[col0], b1 = bias_s[col1];
        float w0 = wa_s[col0], w1 = wa_s[col1];
        p0 += fast_tanh(acc[nt][0] + b0) * w0 + fast_tanh(acc[nt][1] + b1) * w1;
        p1 += fast_tanh(acc[nt][2] + b0) * w0 + fast_tanh(acc[nt][3] + b1) * w1;
    }
    p0 += __shfl_xor_sync(0xffffffffu, p0, 1);
    p0 += __shfl_xor_sync(0xffffffffu, p0, 2);
    p1 += __shfl_xor_sync(0xffffffffu, p1, 1);
    p1 += __shfl_xor_sync(0xffffffffu, p1, 2);
    __syncthreads();   // Wc reads done (red aliases nothing, but order anyway)
    if (tig == 0) {
        red[wn * 64 + r0] = p0;
        red[wn * 64 + r0 + 8] = p1;
    }
    __syncthreads();
    if (tid < 64) {
        float e = which ? ba[0] : 0.0f;
        float* outp = which ? g_so : g_st;
        outp[tok0 + tid] = red[tid] + red[64 + tid] + e;
    }
}

// ---------------------------------------------------------------------
// Kernel 2: attention (unchanged from R14). tf32 PV, single mma,
// identity cp.async from g_v2, 2 CTAs/SM.
// ---------------------------------------------------------------------
#define ATTN_SMEM (2 * 4096 * 8 + LL * 4 + LL * 4 + ROWS * 4)

__global__ __launch_bounds__(256, 2)
void k_attn(float* __restrict__ out) {
    extern __shared__ float sm[];
    float2* Vd    = (float2*)sm;             // 2 * 4096 float2 = 64 KB
    float*  base_s= (float*)(Vd + 2 * 4096); // 2048 f
    float*  sop   = base_s + LL;             // 2048 f
    float*  S_s   = sop + LL;                // 64 f

    int tid = threadIdx.x;
    int lane = tid & 31, wid = tid >> 5;
    int gid = lane >> 2, tig = lane & 3;
    int wm = wid & 3, wn = wid >> 2;
    int b = blockIdx.x >> 5;
    int row0 = (blockIdx.x & 31) * ROWS;

    const float2* V2g = g_v2 + (size_t)b * NTT * 4096;

#pragma unroll
    for (int r = 0; r < 8; ++r) {
        int chunk = r * 256 + tid;
        cp16(Vd + chunk * 2, V2g + chunk * 2);
    }
    asm volatile("cp.async.commit_group;\n");

    const float* sog = g_so + b * LL;
    const float* mug = g_mult + b * LL;
    for (int i = tid; i < LL; i += 256) {
        base_s[i] = g_base[i];
        unsigned u = __float_as_uint(sog[i]);
        u = (u & ~1u) | (mug[i] > 4.0f ? 1u : 0u);
        sop[i] = __uint_as_float(u);
    }

    int lr0 = wm * 16 + gid;
    int i0 = row0 + lr0, i1 = i0 + 8;
    float st0 = g_st[b * LL + i0];
    float st1 = g_st[b * LL + i1];

    float acc[16][4];
#pragma unroll
    for (int nt = 0; nt < 16; ++nt)
#pragma unroll
        for (int q = 0; q < 4; ++q) acc[nt][q] = 0.0f;
    float sum0 = 0.0f, sum1 = 0.0f;

    for (int t = 0; t < NTT; ++t) {
        asm volatile("cp.async.wait_group 0;\n");
        __syncthreads();

        if (t + 1 < NTT) {
            float2* dn = Vd + ((t + 1) & 1) * 4096;
            const float2* gs = V2g + (size_t)(t + 1) * 4096;
#pragma unroll
            for (int r = 0; r < 8; ++r) {
                int chunk = r * 256 + tid;
                cp16(dn + chunk * 2, gs + chunk * 2);
            }
            asm volatile("cp.async.commit_group;\n");
        }

        const float2* Vb2 = Vd + (t & 1) * 4096;
#pragma unroll
        for (int kb = 0; kb < 4; ++kb) {
            int jA = t * JT + kb * 8 + tig;
            float q0 = sop[jA];
            float q1 = sop[jA + 4];
            float m0 = (__float_as_uint(q0) & 1u) ? 8.0f : 1.0f;
            float m1 = (__float_as_uint(q1) & 1u) ? 8.0f : 1.0f;
            int d00 = i0 - jA;     d00 = (d00 < 0) ? -d00 : d00;
            int d10 = i1 - jA;     d10 = (d10 < 0) ? -d10 : d10;
            int d01 = i0 - jA - 4; d01 = (d01 < 0) ? -d01 : d01;
            int d11 = i1 - jA - 4; d11 = (d11 < 0) ? -d11 : d11;
            float p00 = __expf(base_s[d00] * m0 * (st0 + q0));
            float p10 = __expf(base_s[d10] * m0 * (st1 + q0));
            float p01 = __expf(base_s[d01] * m1 * (st0 + q1));
            float p11 = __expf(base_s[d11] * m1 * (st1 + q1));
            sum0 += p00 + p01;
            sum1 += p10 + p11;
            unsigned a0h = cvt_tf32(p00), a1h = cvt_tf32(p10);
            unsigned a2h = cvt_tf32(p01), a3h = cvt_tf32(p11);

            const float2* Bp = Vb2 + (kb * 4 + tig) * 256 + wn * 128;
            int cx = gid ^ (tig * 4);
#pragma unroll
            for (int nt = 0; nt < 16; ++nt) {
                float2 bb = Bp[(nt * 8) ^ cx];
                mma_tf32(acc[nt], a0h, a1h, a2h, a3h,
                         __float_as_uint(bb.x), __float_as_uint(bb.y));
            }
        }
        __syncthreads();
    }

    sum0 += __shfl_xor_sync(0xffffffffu, sum0, 1);
    sum0 += __shfl_xor_sync(0xffffffffu, sum0, 2);
    sum1 += __shfl_xor_sync(0xffffffffu, sum1, 1);
    sum1 += __shfl_xor_sync(0xffffffffu, sum1, 2);
    if (tig == 0 && wn == 0) {
        S_s[lr0] = sum0;
        S_s[lr0 + 8] = sum1;
    }
    __syncthreads();

    float inv0 = 1.0f / S_s[lr0];
    float inv1 = 1.0f / S_s[lr0 + 8];
    float* Ob = out + ((size_t)b * LL + row0) * HH;
#pragma unroll
    for (int nt = 0; nt < 16; ++nt) {
        int col = wn * 128 + nt * 8 + 2 * tig;
        *(float2*)(Ob + (size_t)lr0 * HH + col) =
            make_float2(acc[nt][0] * inv0, acc[nt][1] * inv0);
        *(float2*)(Ob + (size_t)(lr0 + 8) * HH + col) =
            make_float2(acc[nt][2] * inv1, acc[nt][3] * inv1);
    }
}

// ---------------------------------------------------------------------
extern "C" void kernel_launch(void* const* d_in, const int* in_sizes, int n_in,
                              void* d_out, int out_size) {
    const float* opinion = (const float*)d_in[0];
    const float* text    = (const float*)d_in[1];
    const int*   pos     = (const int*)d_in[2];
    const float* Wt      = (const float*)d_in[3];
    const float* bt      = (const float*)d_in[4];
    const float* Wo      = (const float*)d_in[5];
    const float* wa      = (const float*)d_in[6];
    const float* ba      = (const float*)d_in[7];
    float* out = (float*)d_out;

    cudaFuncSetAttribute(k_attn, cudaFuncAttributeMaxDynamicSharedMemorySize,
                         ATTN_SMEM);
    cudaFuncSetAttribute(k_transform_mma,
                         cudaFuncAttributeMaxDynamicSharedMemorySize, TR_SMEM);

    k_base_mult<<<(BB * LL + 255) / 256, 256>>>(pos);
    k_v2<<<BB * NTT, 256>>>(opinion);
    k_w2<<<16, 256>>>(Wt, Wo);
    k_transform_mma<<<dim3(BB * LL / 64, 2), 256, TR_SMEM>>>(text, opinion, bt, wa, ba);
    k_attn<<<BB * (LL / ROWS), 256, ATTN_SMEM>>>(out);
}